// round 2
// baseline (speedup 1.0000x reference)
#include <cuda_runtime.h>
#include <math.h>

#define BB 8
#define SS 4096
#define NR (BB*SS)      // 32768 rows
#define EE 512
#define MF 256
#define SPLITK 8

// ---------------- scratch (device globals; no allocation allowed) ----------
__device__ float g_xn [(size_t)NR*EE];
__device__ float g_q  [(size_t)NR*EE];
__device__ float g_k  [(size_t)NR*EE];
__device__ float g_v  [(size_t)NR*EE];
__device__ float g_y  [(size_t)NR*EE];
__device__ float g_qp [(size_t)NR*MF];
__device__ float g_kp [(size_t)NR*MF];
__device__ float g_xdq[NR];
__device__ float g_xdk[NR];
__device__ float g_D  [NR];
__device__ float g_ks [BB*MF];
__device__ float g_kptv [(size_t)BB*EE*MF];
__device__ float g_kptvp[(size_t)SPLITK*BB*EE*MF];

// ---------------- LayerNorm: one block per row of 512 ---------------------
__global__ __launch_bounds__(128) void ln_kernel(
    const float* __restrict__ x, const float* __restrict__ gamma,
    const float* __restrict__ beta, float* __restrict__ out)
{
    int row = blockIdx.x;
    const float4* xr = reinterpret_cast<const float4*>(x + (size_t)row*EE);
    int t = threadIdx.x;
    float4 v = xr[t];
    float s  = v.x+v.y+v.z+v.w;
    float s2 = v.x*v.x+v.y*v.y+v.z*v.z+v.w*v.w;
    #pragma unroll
    for (int o=16;o>0;o>>=1){
        s  += __shfl_xor_sync(0xffffffffu, s,  o);
        s2 += __shfl_xor_sync(0xffffffffu, s2, o);
    }
    __shared__ float rs[4], rs2[4];
    int wid = t>>5, lane = t&31;
    if (lane==0){ rs[wid]=s; rs2[wid]=s2; }
    __syncthreads();
    s  = rs[0]+rs[1]+rs[2]+rs[3];
    s2 = rs2[0]+rs2[1]+rs2[2]+rs2[3];
    float mu  = s * (1.f/EE);
    float var = s2*(1.f/EE) - mu*mu;
    float inv = rsqrtf(var + 1e-5f);
    float4 g  = reinterpret_cast<const float4*>(gamma)[t];
    float4 bt = reinterpret_cast<const float4*>(beta)[t];
    float4 o;
    o.x = (v.x-mu)*inv*g.x + bt.x;
    o.y = (v.y-mu)*inv*g.y + bt.y;
    o.z = (v.z-mu)*inv*g.z + bt.z;
    o.w = (v.w-mu)*inv*g.w + bt.w;
    reinterpret_cast<float4*>(out + (size_t)row*EE)[t] = o;
}

// ---------------- NT GEMM: C[r,c] = sum_k A[r,k]*W[c,k] + epilogue --------
// MODE 0: + bias[c]
// MODE 1: expf(acc - xd[r]) * (1/16)
// MODE 2: acc / (D[r] + 1e-8)        (per-batch via blockIdx.z strides)
// MODE 3: + bias[c] + addsrc[r,c]
template<int MODE>
__global__ __launch_bounds__(256) void gemm_nt(
    const float* __restrict__ A, const float* __restrict__ W, float* __restrict__ C,
    int K, int ncols,
    const float* __restrict__ bias, const float* __restrict__ xd,
    const float* __restrict__ Dv, const float* __restrict__ addsrc,
    size_t aB, size_t wB, size_t cB, int dB)
{
    __shared__ float As[8][128];
    __shared__ float Ws[8][128];
    int z = blockIdx.z;
    A += (size_t)z*aB; W += (size_t)z*wB; C += (size_t)z*cB;
    const float* Dz = (MODE==2) ? (Dv + (size_t)z*dB) : nullptr;

    int tid = threadIdx.x;
    int rowBase = blockIdx.x*128;
    int colBase = blockIdx.y*128;
    int lr = tid>>1;          // 0..127
    int lk = (tid&1)*4;       // 0 or 4
    int ty = tid>>4, tx = tid&15;

    float acc[8][8];
    #pragma unroll
    for (int i=0;i<8;i++)
        #pragma unroll
        for (int j=0;j<8;j++) acc[i][j]=0.f;

    const float* Aptr = A + (size_t)(rowBase+lr)*K + lk;
    const float* Wptr = W + (size_t)(colBase+lr)*K + lk;

    for (int k0=0;k0<K;k0+=8){
        float4 av = *reinterpret_cast<const float4*>(Aptr + k0);
        float4 wv = *reinterpret_cast<const float4*>(Wptr + k0);
        __syncthreads();
        As[lk+0][lr]=av.x; As[lk+1][lr]=av.y; As[lk+2][lr]=av.z; As[lk+3][lr]=av.w;
        Ws[lk+0][lr]=wv.x; Ws[lk+1][lr]=wv.y; Ws[lk+2][lr]=wv.z; Ws[lk+3][lr]=wv.w;
        __syncthreads();
        #pragma unroll
        for (int kk=0;kk<8;kk++){
            float a[8], b[8];
            *(float4*)&a[0] = *(const float4*)&As[kk][ty*8];
            *(float4*)&a[4] = *(const float4*)&As[kk][ty*8+4];
            *(float4*)&b[0] = *(const float4*)&Ws[kk][tx*8];
            *(float4*)&b[4] = *(const float4*)&Ws[kk][tx*8+4];
            #pragma unroll
            for (int i=0;i<8;i++)
                #pragma unroll
                for (int j=0;j<8;j++)
                    acc[i][j] = fmaf(a[i], b[j], acc[i][j]);
        }
    }

    #pragma unroll
    for (int i=0;i<8;i++){
        int r = rowBase + ty*8 + i;
        float xv=0.f, dinv=1.f;
        if (MODE==1) xv = xd[r];
        if (MODE==2) dinv = 1.f/(Dz[r]+1e-8f);
        #pragma unroll
        for (int j=0;j<8;j+=4){
            int c = colBase + tx*8 + j;
            float* ap = &acc[i][j];
            float4 o;
            if (MODE==0){
                float4 bv = *reinterpret_cast<const float4*>(bias + c);
                o.x=ap[0]+bv.x; o.y=ap[1]+bv.y; o.z=ap[2]+bv.z; o.w=ap[3]+bv.w;
            } else if (MODE==1){
                o.x=expf(ap[0]-xv)*0.0625f; o.y=expf(ap[1]-xv)*0.0625f;
                o.z=expf(ap[2]-xv)*0.0625f; o.w=expf(ap[3]-xv)*0.0625f;
            } else if (MODE==2){
                o.x=ap[0]*dinv; o.y=ap[1]*dinv; o.z=ap[2]*dinv; o.w=ap[3]*dinv;
            } else {
                float4 bv = *reinterpret_cast<const float4*>(bias + c);
                float4 sv = *reinterpret_cast<const float4*>(addsrc + (size_t)r*ncols + c);
                o.x=ap[0]+bv.x+sv.x; o.y=ap[1]+bv.y+sv.y;
                o.z=ap[2]+bv.z+sv.z; o.w=ap[3]+bv.w+sv.w;
            }
            *reinterpret_cast<float4*>(C + (size_t)r*ncols + c) = o;
        }
    }
}

// ---------------- 0.5*||row||^2 for q and k --------------------------------
__global__ __launch_bounds__(256) void xd_kernel(
    const float* __restrict__ q, const float* __restrict__ k,
    float* __restrict__ xdq, float* __restrict__ xdk)
{
    int row  = blockIdx.x*8 + (threadIdx.x>>5);
    int lane = threadIdx.x&31;
    const float4* qr = reinterpret_cast<const float4*>(q + (size_t)row*EE);
    const float4* kr = reinterpret_cast<const float4*>(k + (size_t)row*EE);
    float sq=0.f, sk=0.f;
    #pragma unroll
    for (int j=0;j<4;j++){
        float4 a = qr[lane + j*32];
        sq += a.x*a.x+a.y*a.y+a.z*a.z+a.w*a.w;
        float4 b = kr[lane + j*32];
        sk += b.x*b.x+b.y*b.y+b.z*b.z+b.w*b.w;
    }
    #pragma unroll
    for (int o=16;o>0;o>>=1){
        sq += __shfl_xor_sync(0xffffffffu, sq, o);
        sk += __shfl_xor_sync(0xffffffffu, sk, o);
    }
    if (lane==0){ xdq[row]=0.5f*sq; xdk[row]=0.5f*sk; }
}

// ---------------- column sums of kp per batch ------------------------------
__global__ __launch_bounds__(256) void ksum_kernel(
    const float* __restrict__ kp, float* __restrict__ out)
{
    int b = blockIdx.x, m0 = blockIdx.y*64;
    int tx = threadIdx.x & 63, ty = threadIdx.x >> 6;
    const float* base = kp + (size_t)b*SS*MF + m0 + tx;
    float s=0.f;
    for (int srow=ty; srow<SS; srow+=4) s += base[(size_t)srow*MF];
    __shared__ float red[4][64];
    red[ty][tx]=s;
    __syncthreads();
    if (ty==0) out[b*MF+m0+tx] = red[0][tx]+red[1][tx]+red[2][tx]+red[3][tx];
}

// ---------------- TN GEMM (split-K): kptv[b,e,m] = sum_s v[b,s,e]*kp[b,s,m]
__global__ __launch_bounds__(256) void gemm_tn_kptv(
    const float* __restrict__ Vm, const float* __restrict__ KP,
    float* __restrict__ Cp)
{
    int eBase = blockIdx.x*128;
    int mBase = blockIdx.y*128;
    int b  = blockIdx.z >> 3;   // SPLITK = 8
    int sk = blockIdx.z & 7;
    const float* Vb = Vm + (size_t)b*SS*EE;
    const float* Kb = KP + (size_t)b*SS*MF;
    int s0 = sk*(SS/SPLITK);
    __shared__ float As[8][128], Bs[8][128];
    int tid = threadIdx.x;
    int kr = tid>>5;
    int c4 = (tid&31)*4;
    int ty = tid>>4, tx = tid&15;

    float acc[8][8];
    #pragma unroll
    for (int i=0;i<8;i++)
        #pragma unroll
        for (int j=0;j<8;j++) acc[i][j]=0.f;

    for (int kk=0; kk<SS/SPLITK; kk+=8){
        int s = s0 + kk + kr;
        float4 av = *reinterpret_cast<const float4*>(Vb + (size_t)s*EE + eBase + c4);
        float4 bv = *reinterpret_cast<const float4*>(Kb + (size_t)s*MF + mBase + c4);
        __syncthreads();
        *(float4*)&As[kr][c4] = av;
        *(float4*)&Bs[kr][c4] = bv;
        __syncthreads();
        #pragma unroll
        for (int q8=0;q8<8;q8++){
            float a[8], b8[8];
            *(float4*)&a[0]  = *(const float4*)&As[q8][ty*8];
            *(float4*)&a[4]  = *(const float4*)&As[q8][ty*8+4];
            *(float4*)&b8[0] = *(const float4*)&Bs[q8][tx*8];
            *(float4*)&b8[4] = *(const float4*)&Bs[q8][tx*8+4];
            #pragma unroll
            for (int i=0;i<8;i++)
                #pragma unroll
                for (int j=0;j<8;j++)
                    acc[i][j] = fmaf(a[i], b8[j], acc[i][j]);
        }
    }
    float* Co = Cp + ((size_t)sk*BB + b)*EE*MF;
    #pragma unroll
    for (int i=0;i<8;i++){
        int e = eBase + ty*8 + i;
        #pragma unroll
        for (int j=0;j<8;j+=4){
            int m = mBase + tx*8 + j;
            *reinterpret_cast<float4*>(Co + (size_t)e*MF + m) =
                make_float4(acc[i][j],acc[i][j+1],acc[i][j+2],acc[i][j+3]);
        }
    }
}

__global__ __launch_bounds__(256) void reduce_kptv(
    const float* __restrict__ p, float* __restrict__ o)
{
    size_t i = (size_t)blockIdx.x*256 + threadIdx.x;
    const size_t st = (size_t)BB*EE*MF;
    float s = 0.f;
    #pragma unroll
    for (int sk=0;sk<SPLITK;sk++) s += p[(size_t)sk*st + i];
    o[i] = s;
}

// ---------------- D[r] = qp[r,:] . ksum[b,:] -------------------------------
__global__ __launch_bounds__(256) void d_kernel(
    const float* __restrict__ qp, const float* __restrict__ ks,
    float* __restrict__ D)
{
    int row  = blockIdx.x*8 + (threadIdx.x>>5);
    int lane = threadIdx.x&31;
    int b = row >> 12;  // row / 4096
    const float4* qr = reinterpret_cast<const float4*>(qp + (size_t)row*MF);
    const float4* kr = reinterpret_cast<const float4*>(ks + b*MF);
    float s=0.f;
    #pragma unroll
    for (int j=0;j<2;j++){
        float4 a=qr[lane+j*32], c=kr[lane+j*32];
        s += a.x*c.x + a.y*c.y + a.z*c.z + a.w*c.w;
    }
    #pragma unroll
    for (int o=16;o>0;o>>=1) s += __shfl_xor_sync(0xffffffffu, s, o);
    if (lane==0) D[row]=s;
}

// ---------------- launch ---------------------------------------------------
extern "C" void kernel_launch(void* const* d_in, const int* in_sizes, int n_in,
                              void* d_out, int out_size)
{
    const float* x     = (const float*)d_in[0];
    const float* qw    = (const float*)d_in[1];
    const float* qb    = (const float*)d_in[2];
    const float* kw    = (const float*)d_in[3];
    const float* kb    = (const float*)d_in[4];
    const float* vw    = (const float*)d_in[5];
    const float* vb    = (const float*)d_in[6];
    const float* pw    = (const float*)d_in[7];
    const float* pb    = (const float*)d_in[8];
    const float* gamma = (const float*)d_in[9];
    const float* beta  = (const float*)d_in[10];
    const float* w     = (const float*)d_in[11];
    float* out = (float*)d_out;

    float *xn,*q,*k,*v,*y,*qp,*kp,*xdq,*xdk,*D,*ks,*kptv,*kptvp;
    cudaGetSymbolAddress((void**)&xn,   g_xn);
    cudaGetSymbolAddress((void**)&q,    g_q);
    cudaGetSymbolAddress((void**)&k,    g_k);
    cudaGetSymbolAddress((void**)&v,    g_v);
    cudaGetSymbolAddress((void**)&y,    g_y);
    cudaGetSymbolAddress((void**)&qp,   g_qp);
    cudaGetSymbolAddress((void**)&kp,   g_kp);
    cudaGetSymbolAddress((void**)&xdq,  g_xdq);
    cudaGetSymbolAddress((void**)&xdk,  g_xdk);
    cudaGetSymbolAddress((void**)&D,    g_D);
    cudaGetSymbolAddress((void**)&ks,   g_ks);
    cudaGetSymbolAddress((void**)&kptv, g_kptv);
    cudaGetSymbolAddress((void**)&kptvp,g_kptvp);

    dim3 blk(256);

    // 1) LayerNorm
    ln_kernel<<<NR,128>>>(x, gamma, beta, xn);

    // 2) q/k/v projections (NT, K=512, 512 cols)
    dim3 gqkv(NR/128, EE/128, 1);
    gemm_nt<0><<<gqkv,blk>>>(xn, qw, q, EE, EE, qb, nullptr, nullptr, nullptr, 0,0,0,0);
    gemm_nt<0><<<gqkv,blk>>>(xn, kw, k, EE, EE, kb, nullptr, nullptr, nullptr, 0,0,0,0);
    gemm_nt<0><<<gqkv,blk>>>(xn, vw, v, EE, EE, vb, nullptr, nullptr, nullptr, 0,0,0,0);

    // 3) row half-norms
    xd_kernel<<<NR/8,256>>>(q, k, xdq, xdk);

    // 4) qp/kp random features (NT, K=512, 256 cols, exp epilogue)
    dim3 gqp(NR/128, MF/128, 1);
    gemm_nt<1><<<gqp,blk>>>(q, w, qp, EE, MF, nullptr, xdq, nullptr, nullptr, 0,0,0,0);
    gemm_nt<1><<<gqp,blk>>>(k, w, kp, EE, MF, nullptr, xdk, nullptr, nullptr, 0,0,0,0);

    // 5) ksum[b,m]
    ksum_kernel<<<dim3(BB, MF/64),blk>>>(kp, ks);

    // 6) kptv[b,e,m] via split-K partials (deterministic), then reduce
    gemm_tn_kptv<<<dim3(EE/128, MF/128, BB*SPLITK),blk>>>(v, kp, kptvp);
    reduce_kptv<<<((size_t)BB*EE*MF)/256,blk>>>(kptvp, kptv);

    // 7) D[r]
    d_kernel<<<NR/8,256>>>(qp, ks, D);

    // 8) y[b,s,e] = (qp @ kptv^T) / (D + eps)   (per-batch NT, K=256)
    dim3 gy(SS/128, EE/128, BB);
    gemm_nt<2><<<gy,blk>>>(qp, kptv, y, MF, EE, nullptr, nullptr, D, nullptr,
                           (size_t)SS*MF, (size_t)EE*MF, (size_t)SS*EE, SS);

    // 9) out = v + y @ pw^T + pb
    gemm_nt<3><<<gqkv,blk>>>(y, pw, out, EE, EE, pb, nullptr, nullptr, v, 0,0,0,0);
}